// round 1
// baseline (speedup 1.0000x reference)
#include <cuda_runtime.h>
#include <cuda_bf16.h>
#include <math.h>

// ---------------- problem constants ----------------
#define BB 4
#define SS 2048
#define DD 1024
#define HH 16
#define HD 64
#define FF 4096
#define EE 8
#define TT (BB*SS)          // 8192 tokens
#define CAP 1024            // int(T/E)
#define LN_EPS 1e-5f
#define INV_SCALE 0.125f    // 1/sqrt(64)

// ---------------- scratch (device globals; no runtime allocation) ----------------
__device__ float g_xn1[TT*DD];
__device__ float g_q[TT*DD];
__device__ float g_k[TT*DD];
__device__ float g_v[TT*DD];
__device__ float g_attn[TT*DD];
__device__ float g_x1[TT*DD];
__device__ float g_xn2[TT*DD];
__device__ float g_probs[TT*EE];
__device__ int   g_route[TT];
__device__ int   g_slot[TT];
__device__ int   g_tokmap[EE*CAP];
__device__ float g_h[(long)EE*CAP*FF];   // 128 MB
__device__ float g_eo[EE*CAP*DD];

// ---------------- LayerNorm: one block per row ----------------
__global__ void ln_kernel(const float* __restrict__ x,
                          const float* __restrict__ g,
                          const float* __restrict__ b,
                          float* __restrict__ out)
{
    int row = blockIdx.x;
    const float* xr = x + (long)row*DD;
    float vals[4];
    float s = 0.f, s2 = 0.f;
#pragma unroll
    for (int i = 0; i < 4; i++) {
        float v = xr[threadIdx.x + i*256];
        vals[i] = v; s += v; s2 += v*v;
    }
    __shared__ float rs[256], rs2[256];
    rs[threadIdx.x] = s; rs2[threadIdx.x] = s2;
    __syncthreads();
    for (int st = 128; st > 0; st >>= 1) {
        if (threadIdx.x < st) { rs[threadIdx.x] += rs[threadIdx.x+st]; rs2[threadIdx.x] += rs2[threadIdx.x+st]; }
        __syncthreads();
    }
    float mean = rs[0] * (1.f/DD);
    float var  = rs2[0] * (1.f/DD) - mean*mean;
    float inv  = rsqrtf(var + LN_EPS);
#pragma unroll
    for (int i = 0; i < 4; i++) {
        int c = threadIdx.x + i*256;
        out[(long)row*DD + c] = (vals[i] - mean) * inv * g[c] + b[c];
    }
}

// ---------------- generic SGEMM: C[z] = act(A[z or gather]@B[z] + bias[z]) (+resid) ----------------
// A: [M,K] rows (optionally gathered via rowmap -> row index into A), B: [K,N], C: [M,N]
#define BM 128
#define BN 128
#define BK 16
#define TM 8
#define TN 8
__global__ __launch_bounds__(256, 2)
void sgemm_kernel(const float* __restrict__ A, const float* __restrict__ Bm,
                  float* __restrict__ C,
                  int M, int N, int K,
                  long sA, long sB, long sC,
                  const float* __restrict__ bias, long sBias,
                  const float* __restrict__ resid,
                  const int* __restrict__ rowmap, long sMap,
                  int act)
{
    int z = blockIdx.z;
    A  += z * sA;
    Bm += z * sB;
    C  += z * sC;
    const float* biasz = bias ? bias + z * sBias : nullptr;
    const int*   mapz  = rowmap ? rowmap + z * sMap : nullptr;
    const float* resz  = resid ? resid + z * sC : nullptr;

    __shared__ float As[BK][BM];
    __shared__ float Bs[BK][BN];

    int bm = blockIdx.y * BM;
    int bn = blockIdx.x * BN;
    int tid = threadIdx.x;
    int tx = tid & 15, ty = tid >> 4;

    float acc[TM][TN];
#pragma unroll
    for (int i = 0; i < TM; i++)
#pragma unroll
        for (int j = 0; j < TN; j++) acc[i][j] = 0.f;

    for (int k0 = 0; k0 < K; k0 += BK) {
        // load A tile (128 rows x 16 k) : 512 float4 slots, 2 per thread
#pragma unroll
        for (int i = 0; i < 2; i++) {
            int slot = tid*2 + i;
            int r = slot >> 2, kv = slot & 3;
            int row = bm + r;
            int arow = mapz ? mapz[row] : row;
            float4 v = *(const float4*)(A + (long)arow*K + k0 + kv*4);
            As[kv*4+0][r] = v.x; As[kv*4+1][r] = v.y;
            As[kv*4+2][r] = v.z; As[kv*4+3][r] = v.w;
        }
        // load B tile (16 k x 128 n)
#pragma unroll
        for (int i = 0; i < 2; i++) {
            int slot = tid*2 + i;
            int kk = slot >> 5, nv = slot & 31;
            float4 v = *(const float4*)(Bm + (long)(k0+kk)*N + bn + nv*4);
            *(float4*)(&Bs[kk][nv*4]) = v;
        }
        __syncthreads();
#pragma unroll
        for (int kk = 0; kk < BK; kk++) {
            float a[TM], bb[TN];
#pragma unroll
            for (int i = 0; i < TM; i++) a[i]  = As[kk][ty*TM+i];
#pragma unroll
            for (int j = 0; j < TN; j++) bb[j] = Bs[kk][tx*TN+j];
#pragma unroll
            for (int i = 0; i < TM; i++)
#pragma unroll
                for (int j = 0; j < TN; j++) acc[i][j] += a[i]*bb[j];
        }
        __syncthreads();
    }

#pragma unroll
    for (int i = 0; i < TM; i++) {
        int row = bm + ty*TM + i;
#pragma unroll
        for (int j = 0; j < TN; j++) {
            int col = bn + tx*TN + j;
            float v = acc[i][j];
            if (biasz) v += biasz[col];
            if (act)   v = 0.5f*v*(1.f + erff(v*0.7071067811865476f));
            long idx = (long)row*N + col;
            if (resz) v += resz[idx];
            C[idx] = v;
        }
    }
}

// ---------------- flash attention, fp32, Br=Bc=64 ----------------
#define ATTN_SMEM ((4*64*65 + 3*64)*4)
__global__ void attn_kernel(const float* __restrict__ q,
                            const float* __restrict__ k,
                            const float* __restrict__ v,
                            float* __restrict__ o)
{
    extern __shared__ float sm[];
    float* Qs = sm;                 // 64x65
    float* Ks = Qs + 64*65;
    float* Vs = Ks + 64*65;
    float* Ps = Vs + 64*65;         // scores/probs 64x65
    float* mrow = Ps + 64*65;       // 64
    float* lrow = mrow + 64;
    float* arow = lrow + 64;

    int qt = blockIdx.x, h = blockIdx.y, b = blockIdx.z;
    int tid = threadIdx.x;
    int tx = tid & 15, ty = tid >> 4;
    long base = (long)b*SS*DD + h*HD;

    // load Q tile
    for (int i = tid; i < 64*16; i += 256) {
        int r = i >> 4, cv = i & 15;
        float4 vv = *(const float4*)(q + base + (long)(qt*64 + r)*DD + cv*4);
        Qs[r*65+cv*4+0] = vv.x; Qs[r*65+cv*4+1] = vv.y;
        Qs[r*65+cv*4+2] = vv.z; Qs[r*65+cv*4+3] = vv.w;
    }
    if (tid < 64) { mrow[tid] = -INFINITY; lrow[tid] = 0.f; }
    float oacc[4][4];
#pragma unroll
    for (int i = 0; i < 4; i++)
#pragma unroll
        for (int j = 0; j < 4; j++) oacc[i][j] = 0.f;
    __syncthreads();

    for (int kt = 0; kt <= qt; kt++) {
        for (int i = tid; i < 64*16; i += 256) {
            int r = i >> 4, cv = i & 15;
            float4 kk4 = *(const float4*)(k + base + (long)(kt*64 + r)*DD + cv*4);
            Ks[r*65+cv*4+0] = kk4.x; Ks[r*65+cv*4+1] = kk4.y;
            Ks[r*65+cv*4+2] = kk4.z; Ks[r*65+cv*4+3] = kk4.w;
            float4 vv4 = *(const float4*)(v + base + (long)(kt*64 + r)*DD + cv*4);
            Vs[r*65+cv*4+0] = vv4.x; Vs[r*65+cv*4+1] = vv4.y;
            Vs[r*65+cv*4+2] = vv4.z; Vs[r*65+cv*4+3] = vv4.w;
        }
        __syncthreads();

        float s[4][4];
#pragma unroll
        for (int i = 0; i < 4; i++)
#pragma unroll
            for (int j = 0; j < 4; j++) s[i][j] = 0.f;
        for (int kk = 0; kk < 64; kk++) {
            float a[4], bb[4];
#pragma unroll
            for (int i = 0; i < 4; i++) a[i]  = Qs[(ty*4+i)*65 + kk];
#pragma unroll
            for (int j = 0; j < 4; j++) bb[j] = Ks[(tx*4+j)*65 + kk];
#pragma unroll
            for (int i = 0; i < 4; i++)
#pragma unroll
                for (int j = 0; j < 4; j++) s[i][j] += a[i]*bb[j];
        }
#pragma unroll
        for (int i = 0; i < 4; i++) {
            int qi = qt*64 + ty*4 + i;
#pragma unroll
            for (int j = 0; j < 4; j++) {
                int kj = kt*64 + tx*4 + j;
                float val = s[i][j] * INV_SCALE;
                if (kj > qi) val = -INFINITY;
                Ps[(ty*4+i)*65 + tx*4+j] = val;
            }
        }
        __syncthreads();

        if (tid < 64) {
            int r = tid;
            float m0 = mrow[r], mx = m0;
            for (int c = 0; c < 64; c++) mx = fmaxf(mx, Ps[r*65+c]);
            float alpha = expf(m0 - mx);
            float sum = 0.f;
            for (int c = 0; c < 64; c++) {
                float p = expf(Ps[r*65+c] - mx);
                Ps[r*65+c] = p; sum += p;
            }
            lrow[r] = lrow[r]*alpha + sum;
            mrow[r] = mx;
            arow[r] = alpha;
        }
        __syncthreads();

#pragma unroll
        for (int i = 0; i < 4; i++) {
            float al = arow[ty*4+i];
#pragma unroll
            for (int j = 0; j < 4; j++) oacc[i][j] *= al;
        }
        for (int c = 0; c < 64; c++) {
            float pv[4], vv[4];
#pragma unroll
            for (int i = 0; i < 4; i++) pv[i] = Ps[(ty*4+i)*65 + c];
#pragma unroll
            for (int j = 0; j < 4; j++) vv[j] = Vs[c*65 + tx*4+j];
#pragma unroll
            for (int i = 0; i < 4; i++)
#pragma unroll
                for (int j = 0; j < 4; j++) oacc[i][j] += pv[i]*vv[j];
        }
        __syncthreads();
    }

#pragma unroll
    for (int i = 0; i < 4; i++) {
        float li = 1.f / lrow[ty*4+i];
#pragma unroll
        for (int j = 0; j < 4; j++)
            o[base + (long)(qt*64 + ty*4 + i)*DD + tx*4 + j] = oacc[i][j] * li;
    }
}

// ---------------- gating: logits->softmax->route (one block per token) ----------------
__global__ void gating_kernel(const float* __restrict__ xn2,
                              const float* __restrict__ Wg,
                              const float* __restrict__ bg,
                              float* __restrict__ probs,
                              int* __restrict__ route)
{
    int t = blockIdx.x;
    const float* xr = xn2 + (long)t*DD;
    float acc[EE];
#pragma unroll
    for (int e = 0; e < EE; e++) acc[e] = 0.f;
    for (int i = threadIdx.x; i < DD; i += 128) {
        float xv = xr[i];
#pragma unroll
        for (int e = 0; e < EE; e++) acc[e] += xv * Wg[i*EE + e];
    }
    __shared__ float red[128][EE];
#pragma unroll
    for (int e = 0; e < EE; e++) red[threadIdx.x][e] = acc[e];
    __syncthreads();
    for (int st = 64; st > 0; st >>= 1) {
        if (threadIdx.x < st)
#pragma unroll
            for (int e = 0; e < EE; e++) red[threadIdx.x][e] += red[threadIdx.x+st][e];
        __syncthreads();
    }
    if (threadIdx.x == 0) {
        float l[EE];
        float mx = -INFINITY; int am = 0;
#pragma unroll
        for (int e = 0; e < EE; e++) {
            float v = red[0][e] + bg[e];
            l[e] = v;
            if (v > mx) { mx = v; am = e; }   // first-max = jnp.argmax
        }
        float s = 0.f;
#pragma unroll
        for (int e = 0; e < EE; e++) { l[e] = expf(l[e]-mx); s += l[e]; }
        float is = 1.f/s;
#pragma unroll
        for (int e = 0; e < EE; e++) probs[(long)t*EE + e] = l[e]*is;
        route[t] = am;
    }
}

// ---------------- deterministic routing: positions, slots, counts, n_dropped ----------------
__global__ void route_kernel(const int* __restrict__ route,
                             int* __restrict__ slot,
                             int* __restrict__ tokmap,
                             float* __restrict__ out_counts,
                             float* __restrict__ out_ndrop)
{
    __shared__ int cnt[256][EE];
    __shared__ int keptsh[256];
    int tid = threadIdx.x;
    int c[EE];
#pragma unroll
    for (int e = 0; e < EE; e++) c[e] = 0;
    int t0 = tid * 32;
    int rl[32];
    for (int i = 0; i < 32; i++) { rl[i] = route[t0+i]; c[rl[i]]++; }
#pragma unroll
    for (int e = 0; e < EE; e++) cnt[tid][e] = c[e];
    for (int i = tid; i < EE*CAP; i += 256) tokmap[i] = 0;
    __syncthreads();

    int base[EE];
#pragma unroll
    for (int e = 0; e < EE; e++) base[e] = 0;
    for (int j = 0; j < tid; j++)
#pragma unroll
        for (int e = 0; e < EE; e++) base[e] += cnt[j][e];

    int kept = 0;
    for (int i = 0; i < 32; i++) {
        int t = t0 + i;
        int e = rl[i];
        int p = base[e]++;
        if (p < CAP) {
            int s = e*CAP + p;
            slot[t] = s;
            tokmap[s] = t;
            kept++;
        } else {
            slot[t] = -1;
        }
    }
    keptsh[tid] = kept;
    __syncthreads();
    for (int st = 128; st > 0; st >>= 1) {
        if (tid < st) keptsh[tid] += keptsh[tid+st];
        __syncthreads();
    }
    if (tid == 0) out_ndrop[0] = (float)(TT - keptsh[0]);
    if (tid < EE) {
        int tot = 0;
        for (int j = 0; j < 256; j++) tot += cnt[j][tid];
        out_counts[tid] = (float)tot;
    }
}

// ---------------- deterministic prob_sum reduction (one block per expert) ----------------
__global__ void probsum_kernel(const float* __restrict__ probs, float* __restrict__ out)
{
    int e = blockIdx.x, tid = threadIdx.x;
    float s = 0.f;
    for (int t = tid; t < TT; t += 256) s += probs[(long)t*EE + e];
    __shared__ float red[256];
    red[tid] = s;
    __syncthreads();
    for (int st = 128; st > 0; st >>= 1) {
        if (tid < st) red[tid] += red[tid+st];
        __syncthreads();
    }
    if (tid == 0) out[e] = red[0];
}

// ---------------- final combine: out = x1 + (kept ? eo[slot] : xn2) ----------------
__global__ void combine_kernel(const float* __restrict__ x1,
                               const float* __restrict__ xn2,
                               const float* __restrict__ eo,
                               const int* __restrict__ slot,
                               float* __restrict__ out)
{
    long i = (long)blockIdx.x*256 + threadIdx.x;
    int t = (int)(i / DD);
    int d = (int)(i % DD);
    int s = slot[t];
    float add = (s >= 0) ? eo[(long)s*DD + d] : xn2[i];
    out[i] = x1[i] + add;
}

// ---------------- host ----------------
static float* symf(const void* p) { return (float*)p; }

extern "C" void kernel_launch(void* const* d_in, const int* in_sizes, int n_in,
                              void* d_out, int out_size)
{
    const float* x    = (const float*)d_in[0];
    const float* Wq   = (const float*)d_in[2];
    const float* Wk   = (const float*)d_in[3];
    const float* Wv   = (const float*)d_in[4];
    const float* Wo   = (const float*)d_in[5];
    const float* ln1g = (const float*)d_in[6];
    const float* ln1b = (const float*)d_in[7];
    const float* ln2g = (const float*)d_in[8];
    const float* ln2b = (const float*)d_in[9];
    const float* Wg   = (const float*)d_in[10];
    const float* bg   = (const float*)d_in[11];
    const float* W1   = (const float*)d_in[12];
    const float* b1   = (const float*)d_in[13];
    const float* W2   = (const float*)d_in[14];
    const float* b2   = (const float*)d_in[15];

    float* out_x = (float*)d_out;
    float* out_counts = out_x + (long)TT*DD;
    float* out_psum   = out_counts + EE;
    float* out_ndrop  = out_psum + EE;

    void *p_xn1, *p_q, *p_k, *p_v, *p_attn, *p_x1, *p_xn2, *p_probs,
         *p_route, *p_slot, *p_tokmap, *p_h, *p_eo;
    cudaGetSymbolAddress(&p_xn1, g_xn1);
    cudaGetSymbolAddress(&p_q, g_q);
    cudaGetSymbolAddress(&p_k, g_k);
    cudaGetSymbolAddress(&p_v, g_v);
    cudaGetSymbolAddress(&p_attn, g_attn);
    cudaGetSymbolAddress(&p_x1, g_x1);
    cudaGetSymbolAddress(&p_xn2, g_xn2);
    cudaGetSymbolAddress(&p_probs, g_probs);
    cudaGetSymbolAddress(&p_route, g_route);
    cudaGetSymbolAddress(&p_slot, g_slot);
    cudaGetSymbolAddress(&p_tokmap, g_tokmap);
    cudaGetSymbolAddress(&p_h, g_h);
    cudaGetSymbolAddress(&p_eo, g_eo);

    float* xn1 = (float*)p_xn1;  float* q = (float*)p_q;
    float* k   = (float*)p_k;    float* v = (float*)p_v;
    float* attn= (float*)p_attn; float* x1 = (float*)p_x1;
    float* xn2 = (float*)p_xn2;  float* probs = (float*)p_probs;
    int* route = (int*)p_route;  int* slot = (int*)p_slot;
    int* tokmap= (int*)p_tokmap; float* hbuf = (float*)p_h;
    float* eo  = (float*)p_eo;

    static int attr_done = 0;
    if (!attr_done) {
        cudaFuncSetAttribute(attn_kernel, cudaFuncAttributeMaxDynamicSharedMemorySize, ATTN_SMEM);
        attr_done = 1;
    }

    // 1. LN1
    ln_kernel<<<TT, 256>>>(x, ln1g, ln1b, xn1);

    // 2. Q,K,V projections
    dim3 gproj(DD/BN, TT/BM, 1);
    sgemm_kernel<<<gproj, 256>>>(xn1, Wq, q, TT, DD, DD, 0, 0, 0, nullptr, 0, nullptr, nullptr, 0, 0);
    sgemm_kernel<<<gproj, 256>>>(xn1, Wk, k, TT, DD, DD, 0, 0, 0, nullptr, 0, nullptr, nullptr, 0, 0);
    sgemm_kernel<<<gproj, 256>>>(xn1, Wv, v, TT, DD, DD, 0, 0, 0, nullptr, 0, nullptr, nullptr, 0, 0);

    // 3. attention
    attn_kernel<<<dim3(SS/64, HH, BB), 256, ATTN_SMEM>>>(q, k, v, attn);

    // 4. x1 = x + attn @ Wo
    sgemm_kernel<<<gproj, 256>>>(attn, Wo, x1, TT, DD, DD, 0, 0, 0, nullptr, 0, x, nullptr, 0, 0);

    // 5. LN2
    ln_kernel<<<TT, 256>>>(x1, ln2g, ln2b, xn2);

    // 6. gating
    gating_kernel<<<TT, 128>>>(xn2, Wg, bg, probs, route);

    // 7. routing (single deterministic block)
    route_kernel<<<1, 256>>>(route, slot, tokmap, out_counts, out_ndrop);

    // 8. prob sums
    probsum_kernel<<<EE, 256>>>(probs, out_psum);

    // 9. expert GEMM1: h = gelu(gather(xn2)@W1 + b1)   [E z-batched]
    dim3 g1(FF/BN, CAP/BM, EE);
    sgemm_kernel<<<g1, 256>>>(xn2, W1, hbuf, CAP, FF, DD,
                              0, (long)DD*FF, (long)CAP*FF,
                              b1, FF, nullptr, tokmap, CAP, 1);

    // 10. expert GEMM2: eo = h@W2 + b2
    dim3 g2(DD/BN, CAP/BM, EE);
    sgemm_kernel<<<g2, 256>>>(hbuf, W2, eo, CAP, DD, FF,
                              (long)CAP*FF, (long)FF*DD, (long)CAP*DD,
                              b2, DD, nullptr, nullptr, 0, 0);

    // 11. combine into output
    combine_kernel<<<(TT*DD)/256, 256>>>(x1, xn2, eo, slot, out_x);
}

// round 2
// speedup vs baseline: 1.4055x; 1.4055x over previous
#include <cuda_runtime.h>
#include <cuda_bf16.h>
#include <math.h>

// ---------------- problem constants ----------------
#define BB 4
#define SS 2048
#define DD 1024
#define HH 16
#define HD 64
#define FF 4096
#define EE 8
#define TT (BB*SS)          // 8192 tokens
#define CAP 1024            // int(T/E)
#define LN_EPS 1e-5f
#define INV_SCALE 0.125f    // 1/sqrt(64)

// ---------------- scratch (device globals; no runtime allocation) ----------------
__device__ float g_xn1[TT*DD];
__device__ float g_q[TT*DD];
__device__ float g_k[TT*DD];
__device__ float g_v[TT*DD];
__device__ float g_attn[TT*DD];
__device__ float g_x1[TT*DD];
__device__ float g_xn2[TT*DD];
__device__ float g_probs[TT*EE];
__device__ int   g_route[TT];
__device__ int   g_slot[TT];
__device__ int   g_tokmap[EE*CAP];
__device__ float g_h[(long)EE*CAP*FF];   // 128 MB
__device__ float g_eo[EE*CAP*DD];

// ---------------- LayerNorm: one block per row ----------------
__global__ void ln_kernel(const float* __restrict__ x,
                          const float* __restrict__ g,
                          const float* __restrict__ b,
                          float* __restrict__ out)
{
    int row = blockIdx.x;
    const float* xr = x + (long)row*DD;
    float vals[4];
    float s = 0.f, s2 = 0.f;
#pragma unroll
    for (int i = 0; i < 4; i++) {
        float v = xr[threadIdx.x + i*256];
        vals[i] = v; s += v; s2 += v*v;
    }
    __shared__ float rs[256], rs2[256];
    rs[threadIdx.x] = s; rs2[threadIdx.x] = s2;
    __syncthreads();
    for (int st = 128; st > 0; st >>= 1) {
        if (threadIdx.x < st) { rs[threadIdx.x] += rs[threadIdx.x+st]; rs2[threadIdx.x] += rs2[threadIdx.x+st]; }
        __syncthreads();
    }
    float mean = rs[0] * (1.f/DD);
    float var  = rs2[0] * (1.f/DD) - mean*mean;
    float inv  = rsqrtf(var + LN_EPS);
#pragma unroll
    for (int i = 0; i < 4; i++) {
        int c = threadIdx.x + i*256;
        out[(long)row*DD + c] = (vals[i] - mean) * inv * g[c] + b[c];
    }
}

// ---------------- fp32 SGEMM (upstream of router: must stay fp32-accurate) ----------------
#define BM 128
#define BN 128
#define BK 16
#define TM 8
#define TN 8
__global__ __launch_bounds__(256, 2)
void sgemm_kernel(const float* __restrict__ A, const float* __restrict__ Bm,
                  float* __restrict__ C,
                  int M, int N, int K,
                  long sA, long sB, long sC,
                  const float* __restrict__ bias, long sBias,
                  const float* __restrict__ resid,
                  const int* __restrict__ rowmap, long sMap,
                  int act)
{
    int z = blockIdx.z;
    A  += z * sA;
    Bm += z * sB;
    C  += z * sC;
    const float* biasz = bias ? bias + z * sBias : nullptr;
    const int*   mapz  = rowmap ? rowmap + z * sMap : nullptr;
    const float* resz  = resid ? resid + z * sC : nullptr;

    __shared__ float As[BK][BM];
    __shared__ float Bs[BK][BN];

    int bm = blockIdx.y * BM;
    int bn = blockIdx.x * BN;
    int tid = threadIdx.x;
    int tx = tid & 15, ty = tid >> 4;

    float acc[TM][TN];
#pragma unroll
    for (int i = 0; i < TM; i++)
#pragma unroll
        for (int j = 0; j < TN; j++) acc[i][j] = 0.f;

    for (int k0 = 0; k0 < K; k0 += BK) {
#pragma unroll
        for (int i = 0; i < 2; i++) {
            int slot = tid*2 + i;
            int r = slot >> 2, kv = slot & 3;
            int row = bm + r;
            int arow = mapz ? mapz[row] : row;
            float4 v = *(const float4*)(A + (long)arow*K + k0 + kv*4);
            As[kv*4+0][r] = v.x; As[kv*4+1][r] = v.y;
            As[kv*4+2][r] = v.z; As[kv*4+3][r] = v.w;
        }
#pragma unroll
        for (int i = 0; i < 2; i++) {
            int slot = tid*2 + i;
            int kk = slot >> 5, nv = slot & 31;
            float4 v = *(const float4*)(Bm + (long)(k0+kk)*N + bn + nv*4);
            *(float4*)(&Bs[kk][nv*4]) = v;
        }
        __syncthreads();
#pragma unroll
        for (int kk = 0; kk < BK; kk++) {
            float a[TM], bb[TN];
#pragma unroll
            for (int i = 0; i < TM; i++) a[i]  = As[kk][ty*TM+i];
#pragma unroll
            for (int j = 0; j < TN; j++) bb[j] = Bs[kk][tx*TN+j];
#pragma unroll
            for (int i = 0; i < TM; i++)
#pragma unroll
                for (int j = 0; j < TN; j++) acc[i][j] += a[i]*bb[j];
        }
        __syncthreads();
    }

#pragma unroll
    for (int i = 0; i < TM; i++) {
        int row = bm + ty*TM + i;
#pragma unroll
        for (int j = 0; j < TN; j++) {
            int col = bn + tx*TN + j;
            float v = acc[i][j];
            if (biasz) v += biasz[col];
            if (act)   v = 0.5f*v*(1.f + erff(v*0.7071067811865476f));
            long idx = (long)row*N + col;
            if (resz) v += resz[idx];
            C[idx] = v;
        }
    }
}

// ---------------- TF32 tensor-core GEMM (expert FF, downstream of router) ----------------
// C = act(gather(A) @ B + bias). Tiles: block 128x128x16, 8 warps of 64x32,
// mma.sync.m16n8k8.tf32. Double-buffered smem, 132-float row stride
// (conflict-free fragment loads).
__device__ __forceinline__ float f2tf(float f) {
    unsigned u;
    asm("cvt.rna.tf32.f32 %0, %1;" : "=r"(u) : "f"(f));
    return __uint_as_float(u);
}

__global__ __launch_bounds__(256, 2)
void tf32_gemm_kernel(const float* __restrict__ A, const float* __restrict__ Bm,
                      float* __restrict__ C,
                      int M, int N, int K,
                      long sA, long sB, long sC,
                      const float* __restrict__ bias, long sBias,
                      const int* __restrict__ rowmap, long sMap,
                      int act)
{
    int z = blockIdx.z;
    A  += z * sA;
    Bm += z * sB;
    C  += z * sC;
    const float* biasz = bias ? bias + z * sBias : nullptr;
    const int*   mapz  = rowmap ? rowmap + z * sMap : nullptr;

    __shared__ float As[2][16][132];
    __shared__ float Bs[2][16][132];

    int bm = blockIdx.y * 128;
    int bn = blockIdx.x * 128;
    int tid  = threadIdx.x;
    int warp = tid >> 5, lane = tid & 31;
    int wm = (warp >> 2) * 64;   // 0 / 64
    int wn = (warp & 3) * 32;    // 0,32,64,96
    int grp = lane >> 2, tig = lane & 3;

    float acc[4][4][4];
#pragma unroll
    for (int i = 0; i < 4; i++)
#pragma unroll
        for (int j = 0; j < 4; j++)
#pragma unroll
            for (int r = 0; r < 4; r++) acc[i][j][r] = 0.f;

    int nk = K >> 4;
    float4 ar[2], br[2];

    // ---- prologue: load tile 0 ----
#pragma unroll
    for (int i = 0; i < 2; i++) {
        int s = tid + i*256;
        int r = s >> 2, kv = s & 3;
        int arow = mapz ? mapz[bm + r] : (bm + r);
        ar[i] = *(const float4*)(A + (long)arow*K + kv*4);
        int kk = s >> 5, nv = s & 31;
        br[i] = *(const float4*)(Bm + (long)kk*N + bn + nv*4);
    }
#pragma unroll
    for (int i = 0; i < 2; i++) {
        int s = tid + i*256;
        int r = s >> 2, kv = s & 3;
        As[0][kv*4+0][r] = f2tf(ar[i].x); As[0][kv*4+1][r] = f2tf(ar[i].y);
        As[0][kv*4+2][r] = f2tf(ar[i].z); As[0][kv*4+3][r] = f2tf(ar[i].w);
        int kk = s >> 5, nv = s & 31;
        Bs[0][kk][nv*4+0] = f2tf(br[i].x); Bs[0][kk][nv*4+1] = f2tf(br[i].y);
        Bs[0][kk][nv*4+2] = f2tf(br[i].z); Bs[0][kk][nv*4+3] = f2tf(br[i].w);
    }
    __syncthreads();

    for (int kt = 0; kt < nk; kt++) {
        int st = kt & 1;
        // prefetch next tile into registers
        if (kt + 1 < nk) {
            int k0 = (kt + 1) << 4;
#pragma unroll
            for (int i = 0; i < 2; i++) {
                int s = tid + i*256;
                int r = s >> 2, kv = s & 3;
                int arow = mapz ? mapz[bm + r] : (bm + r);
                ar[i] = *(const float4*)(A + (long)arow*K + k0 + kv*4);
                int kk = s >> 5, nv = s & 31;
                br[i] = *(const float4*)(Bm + (long)(k0+kk)*N + bn + nv*4);
            }
        }
        // ---- compute 2 k-steps of m16n8k8 ----
#pragma unroll
        for (int ks = 0; ks < 2; ks++) {
            unsigned af[4][4], bf[4][2];
#pragma unroll
            for (int mi = 0; mi < 4; mi++) {
                int mb = wm + mi*16;
                af[mi][0] = __float_as_uint(As[st][ks*8 + tig    ][mb + grp    ]);
                af[mi][1] = __float_as_uint(As[st][ks*8 + tig    ][mb + grp + 8]);
                af[mi][2] = __float_as_uint(As[st][ks*8 + tig + 4][mb + grp    ]);
                af[mi][3] = __float_as_uint(As[st][ks*8 + tig + 4][mb + grp + 8]);
            }
#pragma unroll
            for (int ni = 0; ni < 4; ni++) {
                int nb = wn + ni*8;
                bf[ni][0] = __float_as_uint(Bs[st][ks*8 + tig    ][nb + grp]);
                bf[ni][1] = __float_as_uint(Bs[st][ks*8 + tig + 4][nb + grp]);
            }
#pragma unroll
            for (int mi = 0; mi < 4; mi++)
#pragma unroll
                for (int ni = 0; ni < 4; ni++) {
                    asm volatile(
                        "mma.sync.aligned.m16n8k8.row.col.f32.tf32.tf32.f32 "
                        "{%0,%1,%2,%3}, {%4,%5,%6,%7}, {%8,%9}, {%0,%1,%2,%3};"
                        : "+f"(acc[mi][ni][0]), "+f"(acc[mi][ni][1]),
                          "+f"(acc[mi][ni][2]), "+f"(acc[mi][ni][3])
                        : "r"(af[mi][0]), "r"(af[mi][1]), "r"(af[mi][2]), "r"(af[mi][3]),
                          "r"(bf[ni][0]), "r"(bf[ni][1]));
                }
        }
        // store prefetched tile into the other buffer
        if (kt + 1 < nk) {
            int sn = (kt + 1) & 1;
#pragma unroll
            for (int i = 0; i < 2; i++) {
                int s = tid + i*256;
                int r = s >> 2, kv = s & 3;
                As[sn][kv*4+0][r] = f2tf(ar[i].x); As[sn][kv*4+1][r] = f2tf(ar[i].y);
                As[sn][kv*4+2][r] = f2tf(ar[i].z); As[sn][kv*4+3][r] = f2tf(ar[i].w);
                int kk = s >> 5, nv = s & 31;
                Bs[sn][kk][nv*4+0] = f2tf(br[i].x); Bs[sn][kk][nv*4+1] = f2tf(br[i].y);
                Bs[sn][kk][nv*4+2] = f2tf(br[i].z); Bs[sn][kk][nv*4+3] = f2tf(br[i].w);
            }
        }
        __syncthreads();
    }

    // ---- epilogue ----
#pragma unroll
    for (int mi = 0; mi < 4; mi++) {
#pragma unroll
        for (int ni = 0; ni < 4; ni++) {
            int c0 = bn + wn + ni*8 + tig*2;
            float bv0 = biasz ? biasz[c0]   : 0.f;
            float bv1 = biasz ? biasz[c0+1] : 0.f;
#pragma unroll
            for (int h = 0; h < 2; h++) {
                int row = bm + wm + mi*16 + grp + h*8;
                float v0 = acc[mi][ni][h*2+0] + bv0;
                float v1 = acc[mi][ni][h*2+1] + bv1;
                if (act) {
                    v0 = 0.5f*v0*(1.f + erff(v0*0.7071067811865476f));
                    v1 = 0.5f*v1*(1.f + erff(v1*0.7071067811865476f));
                }
                float2 o2; o2.x = v0; o2.y = v1;
                *(float2*)(C + (long)row*N + c0) = o2;
            }
        }
    }
}

// ---------------- flash attention, fp32, Br=Bc=64 ----------------
#define ATTN_SMEM ((4*64*65 + 3*64)*4)
__global__ void attn_kernel(const float* __restrict__ q,
                            const float* __restrict__ k,
                            const float* __restrict__ v,
                            float* __restrict__ o)
{
    extern __shared__ float sm[];
    float* Qs = sm;                 // 64x65
    float* Ks = Qs + 64*65;
    float* Vs = Ks + 64*65;
    float* Ps = Vs + 64*65;         // scores/probs 64x65
    float* mrow = Ps + 64*65;       // 64
    float* lrow = mrow + 64;
    float* arow = lrow + 64;

    int qt = blockIdx.x, h = blockIdx.y, b = blockIdx.z;
    int tid = threadIdx.x;
    int tx = tid & 15, ty = tid >> 4;
    long base = (long)b*SS*DD + h*HD;

    for (int i = tid; i < 64*16; i += 256) {
        int r = i >> 4, cv = i & 15;
        float4 vv = *(const float4*)(q + base + (long)(qt*64 + r)*DD + cv*4);
        Qs[r*65+cv*4+0] = vv.x; Qs[r*65+cv*4+1] = vv.y;
        Qs[r*65+cv*4+2] = vv.z; Qs[r*65+cv*4+3] = vv.w;
    }
    if (tid < 64) { mrow[tid] = -INFINITY; lrow[tid] = 0.f; }
    float oacc[4][4];
#pragma unroll
    for (int i = 0; i < 4; i++)
#pragma unroll
        for (int j = 0; j < 4; j++) oacc[i][j] = 0.f;
    __syncthreads();

    for (int kt = 0; kt <= qt; kt++) {
        for (int i = tid; i < 64*16; i += 256) {
            int r = i >> 4, cv = i & 15;
            float4 kk4 = *(const float4*)(k + base + (long)(kt*64 + r)*DD + cv*4);
            Ks[r*65+cv*4+0] = kk4.x; Ks[r*65+cv*4+1] = kk4.y;
            Ks[r*65+cv*4+2] = kk4.z; Ks[r*65+cv*4+3] = kk4.w;
            float4 vv4 = *(const float4*)(v + base + (long)(kt*64 + r)*DD + cv*4);
            Vs[r*65+cv*4+0] = vv4.x; Vs[r*65+cv*4+1] = vv4.y;
            Vs[r*65+cv*4+2] = vv4.z; Vs[r*65+cv*4+3] = vv4.w;
        }
        __syncthreads();

        float s[4][4];
#pragma unroll
        for (int i = 0; i < 4; i++)
#pragma unroll
            for (int j = 0; j < 4; j++) s[i][j] = 0.f;
        for (int kk = 0; kk < 64; kk++) {
            float a[4], bb[4];
#pragma unroll
            for (int i = 0; i < 4; i++) a[i]  = Qs[(ty*4+i)*65 + kk];
#pragma unroll
            for (int j = 0; j < 4; j++) bb[j] = Ks[(tx*4+j)*65 + kk];
#pragma unroll
            for (int i = 0; i < 4; i++)
#pragma unroll
                for (int j = 0; j < 4; j++) s[i][j] += a[i]*bb[j];
        }
#pragma unroll
        for (int i = 0; i < 4; i++) {
            int qi = qt*64 + ty*4 + i;
#pragma unroll
            for (int j = 0; j < 4; j++) {
                int kj = kt*64 + tx*4 + j;
                float val = s[i][j] * INV_SCALE;
                if (kj > qi) val = -INFINITY;
                Ps[(ty*4+i)*65 + tx*4+j] = val;
            }
        }
        __syncthreads();

        if (tid < 64) {
            int r = tid;
            float m0 = mrow[r], mx = m0;
            for (int c = 0; c < 64; c++) mx = fmaxf(mx, Ps[r*65+c]);
            float alpha = expf(m0 - mx);
            float sum = 0.f;
            for (int c = 0; c < 64; c++) {
                float p = expf(Ps[r*65+c] - mx);
                Ps[r*65+c] = p; sum += p;
            }
            lrow[r] = lrow[r]*alpha + sum;
            mrow[r] = mx;
            arow[r] = alpha;
        }
        __syncthreads();

#pragma unroll
        for (int i = 0; i < 4; i++) {
            float al = arow[ty*4+i];
#pragma unroll
            for (int j = 0; j < 4; j++) oacc[i][j] *= al;
        }
        for (int c = 0; c < 64; c++) {
            float pv[4], vv[4];
#pragma unroll
            for (int i = 0; i < 4; i++) pv[i] = Ps[(ty*4+i)*65 + c];
#pragma unroll
            for (int j = 0; j < 4; j++) vv[j] = Vs[c*65 + tx*4+j];
#pragma unroll
            for (int i = 0; i < 4; i++)
#pragma unroll
                for (int j = 0; j < 4; j++) oacc[i][j] += pv[i]*vv[j];
        }
        __syncthreads();
    }

#pragma unroll
    for (int i = 0; i < 4; i++) {
        float li = 1.f / lrow[ty*4+i];
#pragma unroll
        for (int j = 0; j < 4; j++)
            o[base + (long)(qt*64 + ty*4 + i)*DD + tx*4 + j] = oacc[i][j] * li;
    }
}

// ---------------- gating: logits->softmax->route (one block per token) ----------------
__global__ void gating_kernel(const float* __restrict__ xn2,
                              const float* __restrict__ Wg,
                              const float* __restrict__ bg,
                              float* __restrict__ probs,
                              int* __restrict__ route)
{
    int t = blockIdx.x;
    const float* xr = xn2 + (long)t*DD;
    float acc[EE];
#pragma unroll
    for (int e = 0; e < EE; e++) acc[e] = 0.f;
    for (int i = threadIdx.x; i < DD; i += 128) {
        float xv = xr[i];
#pragma unroll
        for (int e = 0; e < EE; e++) acc[e] += xv * Wg[i*EE + e];
    }
    __shared__ float red[128][EE];
#pragma unroll
    for (int e = 0; e < EE; e++) red[threadIdx.x][e] = acc[e];
    __syncthreads();
    for (int st = 64; st > 0; st >>= 1) {
        if (threadIdx.x < st)
#pragma unroll
            for (int e = 0; e < EE; e++) red[threadIdx.x][e] += red[threadIdx.x+st][e];
        __syncthreads();
    }
    if (threadIdx.x == 0) {
        float l[EE];
        float mx = -INFINITY; int am = 0;
#pragma unroll
        for (int e = 0; e < EE; e++) {
            float v = red[0][e] + bg[e];
            l[e] = v;
            if (v > mx) { mx = v; am = e; }   // first-max = jnp.argmax
        }
        float s = 0.f;
#pragma unroll
        for (int e = 0; e < EE; e++) { l[e] = expf(l[e]-mx); s += l[e]; }
        float is = 1.f/s;
#pragma unroll
        for (int e = 0; e < EE; e++) probs[(long)t*EE + e] = l[e]*is;
        route[t] = am;
    }
}

// ---------------- deterministic routing: positions, slots, counts, n_dropped ----------------
__global__ void route_kernel(const int* __restrict__ route,
                             int* __restrict__ slot,
                             int* __restrict__ tokmap,
                             float* __restrict__ out_counts,
                             float* __restrict__ out_ndrop)
{
    __shared__ int cnt[256][EE];
    __shared__ int keptsh[256];
    int tid = threadIdx.x;
    int c[EE];
#pragma unroll
    for (int e = 0; e < EE; e++) c[e] = 0;
    int t0 = tid * 32;
    int rl[32];
    for (int i = 0; i < 32; i++) { rl[i] = route[t0+i]; c[rl[i]]++; }
#pragma unroll
    for (int e = 0; e < EE; e++) cnt[tid][e] = c[e];
    for (int i = tid; i < EE*CAP; i += 256) tokmap[i] = 0;
    __syncthreads();

    int base[EE];
#pragma unroll
    for (int e = 0; e < EE; e++) base[e] = 0;
    for (int j = 0; j < tid; j++)
#pragma unroll
        for (int e = 0; e < EE; e++) base[e] += cnt[j][e];

    int kept = 0;
    for (int i = 0; i < 32; i++) {
        int t = t0 + i;
        int e = rl[i];
        int p = base[e]++;
        if (p < CAP) {
            int s = e*CAP + p;
            slot[t] = s;
            tokmap[s] = t;
            kept++;
        } else {
            slot[t] = -1;
        }
    }
    keptsh[tid] = kept;
    __syncthreads();
    for (int st = 128; st > 0; st >>= 1) {
        if (tid < st) keptsh[tid] += keptsh[tid+st];
        __syncthreads();
    }
    if (tid == 0) out_ndrop[0] = (float)(TT - keptsh[0]);
    if (tid < EE) {
        int tot = 0;
        for (int j = 0; j < 256; j++) tot += cnt[j][tid];
        out_counts[tid] = (float)tot;
    }
}

// ---------------- deterministic prob_sum reduction (one block per expert) ----------------
__global__ void probsum_kernel(const float* __restrict__ probs, float* __restrict__ out)
{
    int e = blockIdx.x, tid = threadIdx.x;
    float s = 0.f;
    for (int t = tid; t < TT; t += 256) s += probs[(long)t*EE + e];
    __shared__ float red[256];
    red[tid] = s;
    __syncthreads();
    for (int st = 128; st > 0; st >>= 1) {
        if (tid < st) red[tid] += red[tid+st];
        __syncthreads();
    }
    if (tid == 0) out[e] = red[0];
}

// ---------------- final combine: out = x1 + (kept ? eo[slot] : xn2) ----------------
__global__ void combine_kernel(const float* __restrict__ x1,
                               const float* __restrict__ xn2,
                               const float* __restrict__ eo,
                               const int* __restrict__ slot,
                               float* __restrict__ out)
{
    long i = (long)blockIdx.x*256 + threadIdx.x;
    int t = (int)(i / DD);
    int d = (int)(i % DD);
    int s = slot[t];
    float add = (s >= 0) ? eo[(long)s*DD + d] : xn2[i];
    out[i] = x1[i] + add;
}

// ---------------- host ----------------
extern "C" void kernel_launch(void* const* d_in, const int* in_sizes, int n_in,
                              void* d_out, int out_size)
{
    const float* x    = (const float*)d_in[0];
    const float* Wq   = (const float*)d_in[2];
    const float* Wk   = (const float*)d_in[3];
    const float* Wv   = (const float*)d_in[4];
    const float* Wo   = (const float*)d_in[5];
    const float* ln1g = (const float*)d_in[6];
    const float* ln1b = (const float*)d_in[7];
    const float* ln2g = (const float*)d_in[8];
    const float* ln2b = (const float*)d_in[9];
    const float* Wg   = (const float*)d_in[10];
    const float* bg   = (const float*)d_in[11];
    const float* W1   = (const float*)d_in[12];
    const float* b1   = (const float*)d_in[13];
    const float* W2   = (const float*)d_in[14];
    const float* b2   = (const float*)d_in[15];

    float* out_x = (float*)d_out;
    float* out_counts = out_x + (long)TT*DD;
    float* out_psum   = out_counts + EE;
    float* out_ndrop  = out_psum + EE;

    void *p_xn1, *p_q, *p_k, *p_v, *p_attn, *p_x1, *p_xn2, *p_probs,
         *p_route, *p_slot, *p_tokmap, *p_h, *p_eo;
    cudaGetSymbolAddress(&p_xn1, g_xn1);
    cudaGetSymbolAddress(&p_q, g_q);
    cudaGetSymbolAddress(&p_k, g_k);
    cudaGetSymbolAddress(&p_v, g_v);
    cudaGetSymbolAddress(&p_attn, g_attn);
    cudaGetSymbolAddress(&p_x1, g_x1);
    cudaGetSymbolAddress(&p_xn2, g_xn2);
    cudaGetSymbolAddress(&p_probs, g_probs);
    cudaGetSymbolAddress(&p_route, g_route);
    cudaGetSymbolAddress(&p_slot, g_slot);
    cudaGetSymbolAddress(&p_tokmap, g_tokmap);
    cudaGetSymbolAddress(&p_h, g_h);
    cudaGetSymbolAddress(&p_eo, g_eo);

    float* xn1 = (float*)p_xn1;  float* q = (float*)p_q;
    float* k   = (float*)p_k;    float* v = (float*)p_v;
    float* attn= (float*)p_attn; float* x1 = (float*)p_x1;
    float* xn2 = (float*)p_xn2;  float* probs = (float*)p_probs;
    int* route = (int*)p_route;  int* slot = (int*)p_slot;
    int* tokmap= (int*)p_tokmap; float* hbuf = (float*)p_h;
    float* eo  = (float*)p_eo;

    static int attr_done = 0;
    if (!attr_done) {
        cudaFuncSetAttribute(attn_kernel, cudaFuncAttributeMaxDynamicSharedMemorySize, ATTN_SMEM);
        attr_done = 1;
    }

    // 1. LN1
    ln_kernel<<<TT, 256>>>(x, ln1g, ln1b, xn1);

    // 2. Q,K,V projections (fp32: upstream of router)
    dim3 gproj(DD/BN, TT/BM, 1);
    sgemm_kernel<<<gproj, 256>>>(xn1, Wq, q, TT, DD, DD, 0, 0, 0, nullptr, 0, nullptr, nullptr, 0, 0);
    sgemm_kernel<<<gproj, 256>>>(xn1, Wk, k, TT, DD, DD, 0, 0, 0, nullptr, 0, nullptr, nullptr, 0, 0);
    sgemm_kernel<<<gproj, 256>>>(xn1, Wv, v, TT, DD, DD, 0, 0, 0, nullptr, 0, nullptr, nullptr, 0, 0);

    // 3. attention (fp32)
    attn_kernel<<<dim3(SS/64, HH, BB), 256, ATTN_SMEM>>>(q, k, v, attn);

    // 4. x1 = x + attn @ Wo (fp32)
    sgemm_kernel<<<gproj, 256>>>(attn, Wo, x1, TT, DD, DD, 0, 0, 0, nullptr, 0, x, nullptr, 0, 0);

    // 5. LN2
    ln_kernel<<<TT, 256>>>(x1, ln2g, ln2b, xn2);

    // 6. gating (fp32: decides routing)
    gating_kernel<<<TT, 128>>>(xn2, Wg, bg, probs, route);

    // 7. routing (single deterministic block)
    route_kernel<<<1, 256>>>(route, slot, tokmap, out_counts, out_ndrop);

    // 8. prob sums
    probsum_kernel<<<EE, 256>>>(probs, out_psum);

    // 9. expert GEMM1: h = gelu(gather(xn2)@W1 + b1)   [tf32 tensor cores]
    dim3 g1(FF/128, CAP/128, EE);
    tf32_gemm_kernel<<<g1, 256>>>(xn2, W1, hbuf, CAP, FF, DD,
                                  0, (long)DD*FF, (long)CAP*FF,
                                  b1, FF, tokmap, CAP, 1);

    // 10. expert GEMM2: eo = h@W2 + b2   [tf32 tensor cores]
    dim3 g2(DD/128, CAP/128, EE);
    tf32_gemm_kernel<<<g2, 256>>>(hbuf, W2, eo, CAP, DD, FF,
                                  (long)CAP*FF, (long)FF*DD, (long)CAP*DD,
                                  b2, DD, nullptr, 0, 0);

    // 11. combine into output
    combine_kernel<<<(TT*DD)/256, 256>>>(x1, xn2, eo, slot, out_x);
}

// round 3
// speedup vs baseline: 1.5442x; 1.0987x over previous
#include <cuda_runtime.h>
#include <cuda_bf16.h>
#include <math.h>

// ---------------- problem constants ----------------
#define BB 4
#define SS 2048
#define DD 1024
#define HH 16
#define HD 64
#define FF 4096
#define EE 8
#define TT (BB*SS)          // 8192 tokens
#define CAP 1024            // int(T/E)
#define LN_EPS 1e-5f
#define INV_SCALE 0.125f    // 1/sqrt(64)

// ---------------- scratch (device globals; no runtime allocation) ----------------
__device__ float g_xn1[TT*DD];
__device__ float g_q[TT*DD];
__device__ float g_k[TT*DD];
__device__ float g_v[TT*DD];
__device__ float g_attn[TT*DD];
__device__ float g_x1[TT*DD];
__device__ float g_xn2[TT*DD];
__device__ float g_xn2t[TT*DD];            // tf32-rounded copy for expert GEMM A
__device__ float g_probs[TT*EE];
__device__ int   g_route[TT];
__device__ int   g_slot[TT];
__device__ int   g_tokmap[EE*CAP];
__device__ float g_h[(long)EE*CAP*FF];     // 128 MB (stored tf32-rounded)
__device__ float g_eo[EE*CAP*DD];
__device__ float g_w1t[(long)EE*DD*FF];    // tf32-rounded W1 (134 MB)
__device__ float g_w2t[(long)EE*FF*DD];    // tf32-rounded W2 (134 MB)

__device__ __forceinline__ float f2tf(float f) {
    unsigned u;
    asm("cvt.rna.tf32.f32 %0, %1;" : "=r"(u) : "f"(f));
    return __uint_as_float(u);
}

// ---------------- tf32 pre-rounding (vectorized) ----------------
__global__ void round4_kernel(const float4* __restrict__ in, float4* __restrict__ out, long n4)
{
    long i = (long)blockIdx.x*256 + threadIdx.x;
    if (i < n4) {
        float4 v = in[i];
        v.x = f2tf(v.x); v.y = f2tf(v.y); v.z = f2tf(v.z); v.w = f2tf(v.w);
        out[i] = v;
    }
}

// ---------------- LayerNorm: one block per row (optional tf32-rounded 2nd output) ----------------
__global__ void ln_kernel(const float* __restrict__ x,
                          const float* __restrict__ g,
                          const float* __restrict__ b,
                          float* __restrict__ out,
                          float* __restrict__ out_t)
{
    int row = blockIdx.x;
    const float* xr = x + (long)row*DD;
    float vals[4];
    float s = 0.f, s2 = 0.f;
#pragma unroll
    for (int i = 0; i < 4; i++) {
        float v = xr[threadIdx.x + i*256];
        vals[i] = v; s += v; s2 += v*v;
    }
    __shared__ float rs[256], rs2[256];
    rs[threadIdx.x] = s; rs2[threadIdx.x] = s2;
    __syncthreads();
    for (int st = 128; st > 0; st >>= 1) {
        if (threadIdx.x < st) { rs[threadIdx.x] += rs[threadIdx.x+st]; rs2[threadIdx.x] += rs2[threadIdx.x+st]; }
        __syncthreads();
    }
    float mean = rs[0] * (1.f/DD);
    float var  = rs2[0] * (1.f/DD) - mean*mean;
    float inv  = rsqrtf(var + LN_EPS);
#pragma unroll
    for (int i = 0; i < 4; i++) {
        int c = threadIdx.x + i*256;
        float v = (vals[i] - mean) * inv * g[c] + b[c];
        out[(long)row*DD + c] = v;
        if (out_t) out_t[(long)row*DD + c] = f2tf(v);
    }
}

// ---------------- fp32 SGEMM (upstream of router: must stay fp32-accurate) ----------------
#define BM 128
#define BN 128
#define BK 16
#define TM 8
#define TN 8
__global__ __launch_bounds__(256, 2)
void sgemm_kernel(const float* __restrict__ A, const float* __restrict__ Bm,
                  float* __restrict__ C,
                  int M, int N, int K,
                  const float* __restrict__ resid)
{
    __shared__ float As[BK][BM];
    __shared__ float Bs[BK][BN];

    int bm = blockIdx.y * BM;
    int bn = blockIdx.x * BN;
    int tid = threadIdx.x;
    int tx = tid & 15, ty = tid >> 4;

    float acc[TM][TN];
#pragma unroll
    for (int i = 0; i < TM; i++)
#pragma unroll
        for (int j = 0; j < TN; j++) acc[i][j] = 0.f;

    for (int k0 = 0; k0 < K; k0 += BK) {
#pragma unroll
        for (int i = 0; i < 2; i++) {
            int slot = tid*2 + i;
            int r = slot >> 2, kv = slot & 3;
            float4 v = *(const float4*)(A + (long)(bm+r)*K + k0 + kv*4);
            As[kv*4+0][r] = v.x; As[kv*4+1][r] = v.y;
            As[kv*4+2][r] = v.z; As[kv*4+3][r] = v.w;
        }
#pragma unroll
        for (int i = 0; i < 2; i++) {
            int slot = tid*2 + i;
            int kk = slot >> 5, nv = slot & 31;
            float4 v = *(const float4*)(Bm + (long)(k0+kk)*N + bn + nv*4);
            *(float4*)(&Bs[kk][nv*4]) = v;
        }
        __syncthreads();
#pragma unroll
        for (int kk = 0; kk < BK; kk++) {
            float a[TM], bb[TN];
#pragma unroll
            for (int i = 0; i < TM; i++) a[i]  = As[kk][ty*TM+i];
#pragma unroll
            for (int j = 0; j < TN; j++) bb[j] = Bs[kk][tx*TN+j];
#pragma unroll
            for (int i = 0; i < TM; i++)
#pragma unroll
                for (int j = 0; j < TN; j++) acc[i][j] += a[i]*bb[j];
        }
        __syncthreads();
    }

#pragma unroll
    for (int i = 0; i < TM; i++) {
        int row = bm + ty*TM + i;
#pragma unroll
        for (int j = 0; j < TN; j++) {
            int col = bn + tx*TN + j;
            float v = acc[i][j];
            long idx = (long)row*N + col;
            if (resid) v += resid[idx];
            C[idx] = v;
        }
    }
}

// ---------------- TF32 tensor-core GEMM v2 ----------------
// cp.async 3-stage pipeline, BK=32, conflict-free smem strides.
// A in smem as [m][k] stride 36 floats; B as [k][n] stride 136 floats.
// Inputs must already be tf32-rounded. 8 warps x (64x32) warptiles.
#define TG_STAGES 3
#define TG_AF 4608            // 128*36 floats per A stage
#define TG_BF 4352            // 32*136 floats per B stage
#define TG_STAGEF (TG_AF+TG_BF)
#define TG_SMEM (TG_STAGES*TG_STAGEF*4)

#define CP_ASYNC16(saddr, gptr) \
    asm volatile("cp.async.cg.shared.global [%0], [%1], 16;" :: "r"(saddr), "l"(gptr))

__global__ __launch_bounds__(256, 2)
void tf32_gemm_kernel(const float* __restrict__ A, const float* __restrict__ Bmat,
                      float* __restrict__ C,
                      int N, int K,
                      long sA, long sB, long sC,
                      const float* __restrict__ bias, long sBias,
                      const int* __restrict__ rowmap, long sMap,
                      int act, int roundC)
{
    extern __shared__ float sm[];
    int z = blockIdx.z;
    A    += z * sA;
    Bmat += z * sB;
    C    += z * sC;
    const float* biasz = bias ? bias + z * sBias : nullptr;
    const int*   mapz  = rowmap ? rowmap + z * sMap : nullptr;

    int bm = blockIdx.y * 128;
    int bn = blockIdx.x * 128;
    int tid  = threadIdx.x;
    int warp = tid >> 5, lane = tid & 31;
    int wm = (warp >> 2) * 64;   // 0 / 64
    int wn = (warp & 3) * 32;    // 0,32,64,96
    int grp = lane >> 2, tig = lane & 3;

    unsigned smem_u32 = (unsigned)__cvta_generic_to_shared(sm);

    // --- per-thread loader geometry (fixed across k-tiles) ---
    const float* aptr[4]; unsigned aoff[4];
    const float* bptr[4]; unsigned boff[4];
#pragma unroll
    for (int i = 0; i < 4; i++) {
        int idx = i*256 + tid;
        int r = idx >> 3, ch = idx & 7;           // A: row r (0..127), 16B chunk ch (0..7)
        int arow = mapz ? mapz[bm + r] : (bm + r);
        aptr[i] = A + (long)arow*K + ch*4;
        aoff[i] = (unsigned)((r*36 + ch*4)*4);
        int kr = idx >> 5, nv = idx & 31;         // B: k-row kr (0..31), 16B chunk nv
        bptr[i] = Bmat + (long)kr*N + bn + nv*4;
        boff[i] = (unsigned)((kr*136 + nv*4)*4);
    }

    int nk = K >> 5;  // BK=32

    auto load_stage = [&](int kt, int stg) {
        unsigned abase = smem_u32 + stg*(TG_STAGEF*4);
        unsigned bbase = abase + TG_AF*4;
        int k0 = kt << 5;
#pragma unroll
        for (int i = 0; i < 4; i++) CP_ASYNC16(abase + aoff[i], aptr[i] + k0);
#pragma unroll
        for (int i = 0; i < 4; i++) CP_ASYNC16(bbase + boff[i], bptr[i] + (long)k0*N);
    };

    float acc[4][4][4];
#pragma unroll
    for (int i = 0; i < 4; i++)
#pragma unroll
        for (int j = 0; j < 4; j++)
#pragma unroll
            for (int r = 0; r < 4; r++) acc[i][j][r] = 0.f;

    // --- prologue: stages 0,1 ---
    load_stage(0, 0);
    asm volatile("cp.async.commit_group;");
    load_stage(1, 1);
    asm volatile("cp.async.commit_group;");

    for (int kt = 0; kt < nk; kt++) {
        asm volatile("cp.async.wait_group 1;");
        __syncthreads();

        if (kt + 2 < nk) load_stage(kt + 2, (kt + 2) % TG_STAGES);
        asm volatile("cp.async.commit_group;");

        const float* As = sm + (kt % TG_STAGES)*TG_STAGEF;
        const float* Bs = As + TG_AF;

#pragma unroll
        for (int ks = 0; ks < 4; ks++) {
            unsigned af[4][4], bf[4][2];
#pragma unroll
            for (int mi = 0; mi < 4; mi++) {
                int r0 = wm + mi*16 + grp;
                af[mi][0] = __float_as_uint(As[(r0    )*36 + ks*8 + tig    ]);
                af[mi][1] = __float_as_uint(As[(r0 + 8)*36 + ks*8 + tig    ]);
                af[mi][2] = __float_as_uint(As[(r0    )*36 + ks*8 + tig + 4]);
                af[mi][3] = __float_as_uint(As[(r0 + 8)*36 + ks*8 + tig + 4]);
            }
#pragma unroll
            for (int ni = 0; ni < 4; ni++) {
                int nb = wn + ni*8 + grp;
                bf[ni][0] = __float_as_uint(Bs[(ks*8 + tig    )*136 + nb]);
                bf[ni][1] = __float_as_uint(Bs[(ks*8 + tig + 4)*136 + nb]);
            }
#pragma unroll
            for (int mi = 0; mi < 4; mi++)
#pragma unroll
                for (int ni = 0; ni < 4; ni++) {
                    asm volatile(
                        "mma.sync.aligned.m16n8k8.row.col.f32.tf32.tf32.f32 "
                        "{%0,%1,%2,%3}, {%4,%5,%6,%7}, {%8,%9}, {%0,%1,%2,%3};"
                        : "+f"(acc[mi][ni][0]), "+f"(acc[mi][ni][1]),
                          "+f"(acc[mi][ni][2]), "+f"(acc[mi][ni][3])
                        : "r"(af[mi][0]), "r"(af[mi][1]), "r"(af[mi][2]), "r"(af[mi][3]),
                          "r"(bf[ni][0]), "r"(bf[ni][1]));
                }
        }
        __syncthreads();
    }

    // ---- epilogue ----
#pragma unroll
    for (int mi = 0; mi < 4; mi++) {
#pragma unroll
        for (int ni = 0; ni < 4; ni++) {
            int c0 = bn + wn + ni*8 + tig*2;
            float bv0 = biasz ? biasz[c0]   : 0.f;
            float bv1 = biasz ? biasz[c0+1] : 0.f;
#pragma unroll
            for (int h = 0; h < 2; h++) {
                int row = bm + wm + mi*16 + grp + h*8;
                float v0 = acc[mi][ni][h*2+0] + bv0;
                float v1 = acc[mi][ni][h*2+1] + bv1;
                if (act) {
                    v0 = 0.5f*v0*(1.f + erff(v0*0.7071067811865476f));
                    v1 = 0.5f*v1*(1.f + erff(v1*0.7071067811865476f));
                }
                if (roundC) { v0 = f2tf(v0); v1 = f2tf(v1); }
                float2 o2; o2.x = v0; o2.y = v1;
                *(float2*)(C + (long)row*N + c0) = o2;
            }
        }
    }
}

// ---------------- flash attention, fp32, Br=Bc=64 ----------------
#define ATTN_SMEM ((4*64*65 + 3*64)*4)
__global__ void attn_kernel(const float* __restrict__ q,
                            const float* __restrict__ k,
                            const float* __restrict__ v,
                            float* __restrict__ o)
{
    extern __shared__ float smf[];
    float* Qs = smf;
    float* Ks = Qs + 64*65;
    float* Vs = Ks + 64*65;
    float* Ps = Vs + 64*65;
    float* mrow = Ps + 64*65;
    float* lrow = mrow + 64;
    float* arow = lrow + 64;

    int qt = blockIdx.x, h = blockIdx.y, b = blockIdx.z;
    int tid = threadIdx.x;
    int tx = tid & 15, ty = tid >> 4;
    long base = (long)b*SS*DD + h*HD;

    for (int i = tid; i < 64*16; i += 256) {
        int r = i >> 4, cv = i & 15;
        float4 vv = *(const float4*)(q + base + (long)(qt*64 + r)*DD + cv*4);
        Qs[r*65+cv*4+0] = vv.x; Qs[r*65+cv*4+1] = vv.y;
        Qs[r*65+cv*4+2] = vv.z; Qs[r*65+cv*4+3] = vv.w;
    }
    if (tid < 64) { mrow[tid] = -INFINITY; lrow[tid] = 0.f; }
    float oacc[4][4];
#pragma unroll
    for (int i = 0; i < 4; i++)
#pragma unroll
        for (int j = 0; j < 4; j++) oacc[i][j] = 0.f;
    __syncthreads();

    for (int kt = 0; kt <= qt; kt++) {
        for (int i = tid; i < 64*16; i += 256) {
            int r = i >> 4, cv = i & 15;
            float4 kk4 = *(const float4*)(k + base + (long)(kt*64 + r)*DD + cv*4);
            Ks[r*65+cv*4+0] = kk4.x; Ks[r*65+cv*4+1] = kk4.y;
            Ks[r*65+cv*4+2] = kk4.z; Ks[r*65+cv*4+3] = kk4.w;
            float4 vv4 = *(const float4*)(v + base + (long)(kt*64 + r)*DD + cv*4);
            Vs[r*65+cv*4+0] = vv4.x; Vs[r*65+cv*4+1] = vv4.y;
            Vs[r*65+cv*4+2] = vv4.z; Vs[r*65+cv*4+3] = vv4.w;
        }
        __syncthreads();

        float s[4][4];
#pragma unroll
        for (int i = 0; i < 4; i++)
#pragma unroll
            for (int j = 0; j < 4; j++) s[i][j] = 0.f;
        for (int kk = 0; kk < 64; kk++) {
            float a[4], bb[4];
#pragma unroll
            for (int i = 0; i < 4; i++) a[i]  = Qs[(ty*4+i)*65 + kk];
#pragma unroll
            for (int j = 0; j < 4; j++) bb[j] = Ks[(tx*4+j)*65 + kk];
#pragma unroll
            for (int i = 0; i < 4; i++)
#pragma unroll
                for (int j = 0; j < 4; j++) s[i][j] += a[i]*bb[j];
        }
#pragma unroll
        for (int i = 0; i < 4; i++) {
            int qi = qt*64 + ty*4 + i;
#pragma unroll
            for (int j = 0; j < 4; j++) {
                int kj = kt*64 + tx*4 + j;
                float val = s[i][j] * INV_SCALE;
                if (kj > qi) val = -INFINITY;
                Ps[(ty*4+i)*65 + tx*4+j] = val;
            }
        }
        __syncthreads();

        if (tid < 64) {
            int r = tid;
            float m0 = mrow[r], mx = m0;
            for (int c = 0; c < 64; c++) mx = fmaxf(mx, Ps[r*65+c]);
            float alpha = expf(m0 - mx);
            float sum = 0.f;
            for (int c = 0; c < 64; c++) {
                float p = expf(Ps[r*65+c] - mx);
                Ps[r*65+c] = p; sum += p;
            }
            lrow[r] = lrow[r]*alpha + sum;
            mrow[r] = mx;
            arow[r] = alpha;
        }
        __syncthreads();

#pragma unroll
        for (int i = 0; i < 4; i++) {
            float al = arow[ty*4+i];
#pragma unroll
            for (int j = 0; j < 4; j++) oacc[i][j] *= al;
        }
        for (int c = 0; c < 64; c++) {
            float pv[4], vv[4];
#pragma unroll
            for (int i = 0; i < 4; i++) pv[i] = Ps[(ty*4+i)*65 + c];
#pragma unroll
            for (int j = 0; j < 4; j++) vv[j] = Vs[c*65 + tx*4+j];
#pragma unroll
            for (int i = 0; i < 4; i++)
#pragma unroll
                for (int j = 0; j < 4; j++) oacc[i][j] += pv[i]*vv[j];
        }
        __syncthreads();
    }

#pragma unroll
    for (int i = 0; i < 4; i++) {
        float li = 1.f / lrow[ty*4+i];
#pragma unroll
        for (int j = 0; j < 4; j++)
            o[base + (long)(qt*64 + ty*4 + i)*DD + tx*4 + j] = oacc[i][j] * li;
    }
}

// ---------------- gating ----------------
__global__ void gating_kernel(const float* __restrict__ xn2,
                              const float* __restrict__ Wg,
                              const float* __restrict__ bg,
                              float* __restrict__ probs,
                              int* __restrict__ route)
{
    int t = blockIdx.x;
    const float* xr = xn2 + (long)t*DD;
    float acc[EE];
#pragma unroll
    for (int e = 0; e < EE; e++) acc[e] = 0.f;
    for (int i = threadIdx.x; i < DD; i += 128) {
        float xv = xr[i];
#pragma unroll
        for (int e = 0; e < EE; e++) acc[e] += xv * Wg[i*EE + e];
    }
    __shared__ float red[128][EE];
#pragma unroll
    for (int e = 0; e < EE; e++) red[threadIdx.x][e] = acc[e];
    __syncthreads();
    for (int st = 64; st > 0; st >>= 1) {
        if (threadIdx.x < st)
#pragma unroll
            for (int e = 0; e < EE; e++) red[threadIdx.x][e] += red[threadIdx.x+st][e];
        __syncthreads();
    }
    if (threadIdx.x == 0) {
        float l[EE];
        float mx = -INFINITY; int am = 0;
#pragma unroll
        for (int e = 0; e < EE; e++) {
            float v = red[0][e] + bg[e];
            l[e] = v;
            if (v > mx) { mx = v; am = e; }
        }
        float s = 0.f;
#pragma unroll
        for (int e = 0; e < EE; e++) { l[e] = expf(l[e]-mx); s += l[e]; }
        float is = 1.f/s;
#pragma unroll
        for (int e = 0; e < EE; e++) probs[(long)t*EE + e] = l[e]*is;
        route[t] = am;
    }
}

// ---------------- deterministic routing ----------------
__global__ void route_kernel(const int* __restrict__ route,
                             int* __restrict__ slot,
                             int* __restrict__ tokmap,
                             float* __restrict__ out_counts,
                             float* __restrict__ out_ndrop)
{
    __shared__ int cnt[256][EE];
    __shared__ int keptsh[256];
    int tid = threadIdx.x;
    int c[EE];
#pragma unroll
    for (int e = 0; e < EE; e++) c[e] = 0;
    int t0 = tid * 32;
    int rl[32];
    for (int i = 0; i < 32; i++) { rl[i] = route[t0+i]; c[rl[i]]++; }
#pragma unroll
    for (int e = 0; e < EE; e++) cnt[tid][e] = c[e];
    for (int i = tid; i < EE*CAP; i += 256) tokmap[i] = 0;
    __syncthreads();

    int base[EE];
#pragma unroll
    for (int e = 0; e < EE; e++) base[e] = 0;
    for (int j = 0; j < tid; j++)
#pragma unroll
        for (int e = 0; e < EE; e++) base[e] += cnt[j][e];

    int kept = 0;
    for (int i = 0; i < 32; i++) {
        int t = t0 + i;
        int e = rl[i];
        int p = base[e]++;
        if (p < CAP) {
            int s = e*CAP + p;
            slot[t] = s;
            tokmap[s] = t;
            kept++;
        } else {
            slot[t] = -1;
        }
    }
    keptsh[tid] = kept;
    __syncthreads();
    for (int st = 128; st > 0; st >>= 1) {
        if (tid < st) keptsh[tid] += keptsh[tid+st];
        __syncthreads();
    }
    if (tid == 0) out_ndrop[0] = (float)(TT - keptsh[0]);
    if (tid < EE) {
        int tot = 0;
        for (int j = 0; j < 256; j++) tot += cnt[j][tid];
        out_counts[tid] = (float)tot;
    }
}

// ---------------- prob_sum ----------------
__global__ void probsum_kernel(const float* __restrict__ probs, float* __restrict__ out)
{
    int e = blockIdx.x, tid = threadIdx.x;
    float s = 0.f;
    for (int t = tid; t < TT; t += 256) s += probs[(long)t*EE + e];
    __shared__ float red[256];
    red[tid] = s;
    __syncthreads();
    for (int st = 128; st > 0; st >>= 1) {
        if (tid < st) red[tid] += red[tid+st];
        __syncthreads();
    }
    if (tid == 0) out[e] = red[0];
}

// ---------------- final combine ----------------
__global__ void combine_kernel(const float* __restrict__ x1,
                               const float* __restrict__ xn2,
                               const float* __restrict__ eo,
                               const int* __restrict__ slot,
                               float* __restrict__ out)
{
    long i = (long)blockIdx.x*256 + threadIdx.x;
    int t = (int)(i / DD);
    int d = (int)(i % DD);
    int s = slot[t];
    float add = (s >= 0) ? eo[(long)s*DD + d] : xn2[i];
    out[i] = x1[i] + add;
}

// ---------------- host ----------------
extern "C" void kernel_launch(void* const* d_in, const int* in_sizes, int n_in,
                              void* d_out, int out_size)
{
    const float* x    = (const float*)d_in[0];
    const float* Wq   = (const float*)d_in[2];
    const float* Wk   = (const float*)d_in[3];
    const float* Wv   = (const float*)d_in[4];
    const float* Wo   = (const float*)d_in[5];
    const float* ln1g = (const float*)d_in[6];
    const float* ln1b = (const float*)d_in[7];
    const float* ln2g = (const float*)d_in[8];
    const float* ln2b = (const float*)d_in[9];
    const float* Wg   = (const float*)d_in[10];
    const float* bg   = (const float*)d_in[11];
    const float* W1   = (const float*)d_in[12];
    const float* b1   = (const float*)d_in[13];
    const float* W2   = (const float*)d_in[14];
    const float* b2   = (const float*)d_in[15];

    float* out_x = (float*)d_out;
    float* out_counts = out_x + (long)TT*DD;
    float* out_psum   = out_counts + EE;
    float* out_ndrop  = out_psum + EE;

    void *p_xn1, *p_q, *p_k, *p_v, *p_attn, *p_x1, *p_xn2, *p_xn2t, *p_probs,
         *p_route, *p_slot, *p_tokmap, *p_h, *p_eo, *p_w1t, *p_w2t;
    cudaGetSymbolAddress(&p_xn1, g_xn1);
    cudaGetSymbolAddress(&p_q, g_q);
    cudaGetSymbolAddress(&p_k, g_k);
    cudaGetSymbolAddress(&p_v, g_v);
    cudaGetSymbolAddress(&p_attn, g_attn);
    cudaGetSymbolAddress(&p_x1, g_x1);
    cudaGetSymbolAddress(&p_xn2, g_xn2);
    cudaGetSymbolAddress(&p_xn2t, g_xn2t);
    cudaGetSymbolAddress(&p_probs, g_probs);
    cudaGetSymbolAddress(&p_route, g_route);
    cudaGetSymbolAddress(&p_slot, g_slot);
    cudaGetSymbolAddress(&p_tokmap, g_tokmap);
    cudaGetSymbolAddress(&p_h, g_h);
    cudaGetSymbolAddress(&p_eo, g_eo);
    cudaGetSymbolAddress(&p_w1t, g_w1t);
    cudaGetSymbolAddress(&p_w2t, g_w2t);

    float* xn1 = (float*)p_xn1;  float* q = (float*)p_q;
    float* k   = (float*)p_k;    float* v = (float*)p_v;
    float* attn= (float*)p_attn; float* x1 = (float*)p_x1;
    float* xn2 = (float*)p_xn2;  float* xn2t = (float*)p_xn2t;
    float* probs = (float*)p_probs;
    int* route = (int*)p_route;  int* slot = (int*)p_slot;
    int* tokmap= (int*)p_tokmap; float* hbuf = (float*)p_h;
    float* eo  = (float*)p_eo;
    float* w1t = (float*)p_w1t;  float* w2t = (float*)p_w2t;

    static int attr_done = 0;
    if (!attr_done) {
        cudaFuncSetAttribute(attn_kernel, cudaFuncAttributeMaxDynamicSharedMemorySize, ATTN_SMEM);
        cudaFuncSetAttribute(tf32_gemm_kernel, cudaFuncAttributeMaxDynamicSharedMemorySize, TG_SMEM);
        attr_done = 1;
    }

    // 0. pre-round expert weights to tf32
    long w4 = (long)EE*DD*FF/4;   // 8.39M float4s
    round4_kernel<<<(int)((w4+255)/256), 256>>>((const float4*)W1, (float4*)w1t, w4);
    round4_kernel<<<(int)((w4+255)/256), 256>>>((const float4*)W2, (float4*)w2t, w4);

    // 1. LN1
    ln_kernel<<<TT, 256>>>(x, ln1g, ln1b, xn1, nullptr);

    // 2. Q,K,V projections (fp32: upstream of router)
    dim3 gproj(DD/BN, TT/BM, 1);
    sgemm_kernel<<<gproj, 256>>>(xn1, Wq, q, TT, DD, DD, nullptr);
    sgemm_kernel<<<gproj, 256>>>(xn1, Wk, k, TT, DD, DD, nullptr);
    sgemm_kernel<<<gproj, 256>>>(xn1, Wv, v, TT, DD, DD, nullptr);

    // 3. attention (fp32)
    attn_kernel<<<dim3(SS/64, HH, BB), 256, ATTN_SMEM>>>(q, k, v, attn);

    // 4. x1 = x + attn @ Wo (fp32)
    sgemm_kernel<<<gproj, 256>>>(attn, Wo, x1, TT, DD, DD, x);

    // 5. LN2 (also emits tf32-rounded copy for expert GEMM)
    ln_kernel<<<TT, 256>>>(x1, ln2g, ln2b, xn2, xn2t);

    // 6. gating (fp32)
    gating_kernel<<<TT, 128>>>(xn2, Wg, bg, probs, route);

    // 7. routing
    route_kernel<<<1, 256>>>(route, slot, tokmap, out_counts, out_ndrop);

    // 8. prob sums
    probsum_kernel<<<EE, 256>>>(probs, out_psum);

    // 9. expert GEMM1: h = round(gelu(gather(xn2t)@w1t + b1))
    dim3 g1(FF/128, CAP/128, EE);
    tf32_gemm_kernel<<<g1, 256, TG_SMEM>>>(xn2t, w1t, hbuf, FF, DD,
                                           0, (long)DD*FF, (long)CAP*FF,
                                           b1, FF, tokmap, CAP, 1, 1);

    // 10. expert GEMM2: eo = h@w2t + b2
    dim3 g2(DD/128, CAP/128, EE);
    tf32_gemm_kernel<<<g2, 256, TG_SMEM>>>(hbuf, w2t, eo, DD, FF,
                                           (long)CAP*FF, (long)FF*DD, (long)CAP*DD,
                                           b2, DD, nullptr, 0, 0, 0);

    // 11. combine
    combine_kernel<<<(TT*DD)/256, 256>>>(x1, xn2, eo, slot, out_x);
}